// round 16
// baseline (speedup 1.0000x reference)
#include <cuda_runtime.h>
#include <cuda_fp16.h>
#include <cstdint>

#define BB      32
#define NN      8192
#define HH      512
#define K2      256
#define TM      128
#define THREADS 512
#define NWARP   16
#define EPSLN   1e-5f
#define SLOPE   0.2f
#define KC      32
#define NCH     (HH / KC)       // 16 k-chunks per tile
#define NRING   3
#define NE      10
#define NTILES  ((NN / TM) * BB)   // 2048
#define GRIDX   148

// B row: 32 fp16 (64 B) + 16 B pad = 80 B (40 halves) -- conflict-free for ldsm
#define BROWH   40
#define BCHUNK  (K2 * 80)               // 20480 B per chunk

// A tile in smem: 128 rows x (512 fp16 = 1024 B + 16 pad) = 1040 B stride
#define AROWB   1040
#define A_SIZE  (TM * AROWB)            // 133120 B

__device__ __half g_W2C[(size_t)NE * NCH * K2 * BROWH];
__device__ float g_LN1[NE * 16];

// ---------------- smem layout (bytes) ----------------
#define A_OFF  0u
#define B0_OFF 133120u                  // 3 x 20480 -> ends 194560
#define EP_OFF 194560u                  // epilogue partials: 2560 floats = 10240 B
#define P_OFF  204800u
#define F_W1    0             // [3][512]
#define F_B1    1536
#define F_G1    2048
#define F_BE1   2560
#define F_B2    3072
#define F_G2    3328
#define F_BE2   3584
#define F_W3    3840          // [256][3]
#define F_PTS   4612          // [128][3]
#define F_MU    4996
#define F_RS    5124
#define F_LC    5252          // 16 LN1 constants
#define F_END   5268
#define MBF_OFF (P_OFF + F_END * 4)    // 3 x full
#define MBE_OFF (MBF_OFF + 24)         // 3 x empty
#define MBP_OFF (MBE_OFF + 24)         // prologue-params staging
#define MBQ_OFF (MBP_OFF + 8)          // epilogue-params staging
#define MBA_OFF (MBQ_OFF + 8)          // 16 x per-chunk A-ready
#define SMEM_TOTAL (MBA_OFF + 128)     // 226064 B
#define PRO_BYTES (6144 + 2048 * 3 + 1536 + 64)   // 13888
#define EPI_BYTES (1024 * 3 + 3072)               // 6144
// epilogue partials (float idx rel. to EP_OFF)
#define E_S     0      // [128][4]
#define E_S2    512    // [128][4]
#define E_O     1024   // [128][4][3]

__device__ __forceinline__ uint32_t smem_u32(const void* p) {
    uint32_t a;
    asm("{ .reg .u64 t; cvta.to.shared.u64 t, %1; cvt.u32.u64 %0, t; }" : "=r"(a) : "l"(p));
    return a;
}
__device__ __forceinline__ float warp_sum(float v) {
#pragma unroll
    for (int o = 16; o; o >>= 1) v += __shfl_xor_sync(0xffffffffu, v, o);
    return v;
}
__device__ __forceinline__ void ldsm4(uint32_t* r, uint32_t addr) {
    asm volatile("ldmatrix.sync.aligned.m8n8.x4.shared.b16 {%0,%1,%2,%3}, [%4];"
                 : "=r"(r[0]), "=r"(r[1]), "=r"(r[2]), "=r"(r[3]) : "r"(addr));
}
__device__ __forceinline__ void mma_f16(float* c, const uint32_t* a, uint32_t b0, uint32_t b1) {
    asm volatile("mma.sync.aligned.m16n8k16.row.col.f32.f16.f16.f32 "
                 "{%0,%1,%2,%3}, {%4,%5,%6,%7}, {%8,%9}, {%0,%1,%2,%3};"
                 : "+f"(c[0]), "+f"(c[1]), "+f"(c[2]), "+f"(c[3])
                 : "r"(a[0]), "r"(a[1]), "r"(a[2]), "r"(a[3]), "r"(b0), "r"(b1));
}
__device__ __forceinline__ void mbar_wait(uint32_t addr, uint32_t parity) {
    asm volatile(
        "{\n\t.reg .pred P;\n\t"
        "WL_%=:\n\t"
        "mbarrier.try_wait.parity.acquire.cta.shared::cta.b64 P, [%0], %1, 0x989680;\n\t"
        "@P bra.uni WD_%=;\n\t"
        "bra.uni WL_%=;\n\t"
        "WD_%=:\n\t}"
        :: "r"(addr), "r"(parity) : "memory");
}
__device__ __forceinline__ void bulk_in(uint32_t dst, const void* src, uint32_t bytes,
                                        uint32_t mbar) {
    asm volatile(
        "cp.async.bulk.shared::cluster.global.mbarrier::complete_tx::bytes "
        "[%0], [%1], %2, [%3];"
        :: "r"(dst), "l"(src), "r"(bytes), "r"(mbar) : "memory");
}
__device__ __forceinline__ void expect_tx(uint32_t mbar, uint32_t bytes) {
    asm volatile("mbarrier.arrive.expect_tx.shared.b64 _, [%0], %1;"
                 :: "r"(mbar), "r"(bytes) : "memory");
}
__device__ __forceinline__ void mbar_arrive(uint32_t mbar) {
    asm volatile("mbarrier.arrive.release.cta.shared::cta.b64 _, [%0];"
                 :: "r"(mbar) : "memory");
}
__device__ __forceinline__ float lrelu(float y) { return fmaxf(y, SLOPE * y); }

// ------------- W2 pack: transpose + fp16 + KC=32 chunk image -------------
__global__ void pack_w2(const float* __restrict__ W2) {
    __shared__ float t[32][33];
    const int e  = blockIdx.z;
    const int kb = blockIdx.x * 32, nb = blockIdx.y * 32;
    const int tx = threadIdx.x, ty = threadIdx.y;
    const float* src = W2 + e * HH * K2;
#pragma unroll
    for (int r = 0; r < 32; r += 8)
        t[ty + r][tx] = src[(kb + ty + r) * K2 + nb + tx];
    __syncthreads();
    const int ch = kb >> 5;
    __half* dst = g_W2C + ((size_t)(e * NCH + ch) * K2) * BROWH;
#pragma unroll
    for (int r = 0; r < 32; r += 8)
        dst[(size_t)(nb + ty + r) * BROWH + tx] = __float2half_rn(t[tx][ty + r]);
}

// ------------- LN1 closed-form constants per expert -------------
__global__ void pack_ln1(const float* __restrict__ W1, const float* __restrict__ b1) {
    __shared__ float red[16][14];
    const int e = blockIdx.x, tid = threadIdx.x;   // 512 threads
    const float* w = W1 + e * 3 * HH;
    const float w0 = w[tid], w1 = w[HH + tid], w2 = w[2 * HH + tid];
    const float bb = b1[e * HH + tid];
    float vals[14] = { w0*w0, w0*w1, w0*w2, w1*w1, w1*w2, w2*w2,
                       w0*bb, w1*bb, w2*bb, w0, w1, w2, bb, bb*bb };
#pragma unroll
    for (int i = 0; i < 14; i++) vals[i] = warp_sum(vals[i]);
    const int wid = tid >> 5, lane = tid & 31;
    if (lane == 0)
#pragma unroll
        for (int i = 0; i < 14; i++) red[wid][i] = vals[i];
    __syncthreads();
    if (tid < 14) {
        float s = 0.f;
#pragma unroll
        for (int wq = 0; wq < 16; wq++) s += red[wq][tid];
        g_LN1[e * 16 + tid] = s;
    }
    if (tid >= 14 && tid < 16) g_LN1[e * 16 + tid] = 0.f;
}

extern __shared__ char smem_raw[];

__global__ __launch_bounds__(THREADS, 1)
void shape_prior_mma(const float* __restrict__ points, const int* __restrict__ cat,
                     const float* __restrict__ W1, const float* __restrict__ b1,
                     const float* __restrict__ g1, const float* __restrict__ be1,
                     const float* __restrict__ b2, const float* __restrict__ g2,
                     const float* __restrict__ be2,
                     const float* __restrict__ W3, const float* __restrict__ b3,
                     float* __restrict__ out)
{
    float* pf = (float*)(smem_raw + P_OFF);
    float* ep = (float*)(smem_raw + EP_OFF);
    const int tid  = threadIdx.x;
    const int wid  = tid >> 5;
    const int lane = tid & 31;
    const int bid  = blockIdx.x;
    const int gx   = gridDim.x;
    const uint32_t sbase = smem_u32(smem_raw);
    const uint32_t pbase = sbase + P_OFF;

    const int nt = (NTILES - bid + gx - 1) / gx;
    if (nt <= 0) return;
    const int totalChunks = nt * NCH;

    if (tid == 0) {
#pragma unroll
        for (int j = 0; j < NRING; j++) {
            asm volatile("mbarrier.init.shared.b64 [%0], 1;"
                         :: "r"(sbase + MBF_OFF + 8u * j) : "memory");
            asm volatile("mbarrier.init.shared.b64 [%0], %1;"
                         :: "r"(sbase + MBE_OFF + 8u * j), "r"(NWARP) : "memory");
        }
        asm volatile("mbarrier.init.shared.b64 [%0], 1;"
                     :: "r"(sbase + MBP_OFF) : "memory");
        asm volatile("mbarrier.init.shared.b64 [%0], 1;"
                     :: "r"(sbase + MBQ_OFF) : "memory");
#pragma unroll
        for (int j = 0; j < NCH; j++)
            asm volatile("mbarrier.init.shared.b64 [%0], 32;"
                         :: "r"(sbase + MBA_OFF + 8u * j) : "memory");
    }
    __syncthreads();

    auto issue_pro = [&](int T) {
        const int bI = T >> 6, mm0 = (T & 63) * TM;
        const int cc = __ldg(cat + bI);
        const uint32_t mb = sbase + MBP_OFF;
        expect_tx(mb, PRO_BYTES);
        bulk_in(pbase + F_W1  * 4, W1  + (size_t)cc * 3 * HH, 6144, mb);
        bulk_in(pbase + F_B1  * 4, b1  + (size_t)cc * HH,     2048, mb);
        bulk_in(pbase + F_G1  * 4, g1  + (size_t)cc * HH,     2048, mb);
        bulk_in(pbase + F_BE1 * 4, be1 + (size_t)cc * HH,     2048, mb);
        bulk_in(pbase + F_PTS * 4, points + (size_t)(bI * NN + mm0) * 3, 1536, mb);
        bulk_in(pbase + F_LC  * 4, g_LN1 + cc * 16, 64, mb);
    };
    auto issue_epi = [&](int T) {
        const int cc = __ldg(cat + (T >> 6));
        const uint32_t mb = sbase + MBQ_OFF;
        expect_tx(mb, EPI_BYTES);
        bulk_in(pbase + F_B2  * 4, b2  + (size_t)cc * K2,     1024, mb);
        bulk_in(pbase + F_G2  * 4, g2  + (size_t)cc * K2,     1024, mb);
        bulk_in(pbase + F_BE2 * 4, be2 + (size_t)cc * K2,     1024, mb);
        bulk_in(pbase + F_W3  * 4, W3  + (size_t)cc * K2 * 3, 3072, mb);
    };
    auto fill_B = [&](int g) {   // global chunk index
        const int T  = bid + (g >> 4) * gx;
        const int cc = __ldg(cat + (T >> 6));
        const int sl = g % NRING;
        const uint32_t mb = sbase + MBF_OFF + 8u * sl;
        expect_tx(mb, BCHUNK);
        bulk_in(sbase + B0_OFF + (uint32_t)BCHUNK * sl,
                g_W2C + ((size_t)(cc * NCH + (g & 15)) * K2) * BROWH, BCHUNK, mb);
    };

    if (tid == 0) {
        issue_pro(bid);
        issue_epi(bid);
#pragma unroll
        for (int j = 0; j < NRING; j++)
            if (j < totalChunks) fill_B(j);
    }

    // warp tile 32x64: wm = wid>>2 (rows wm*32..), wn = wid&3 (cols wn*64..)
    const int wm = wid >> 2, wn = wid & 3;
    const int grp = lane >> 3, r8 = lane & 7;
    const uint32_t a_lane = sbase + A_OFF
                          + (uint32_t)((r8 + ((grp & 1) << 3) + wm * 32) * AROWB
                                       + (grp >> 1) * 16);
    const uint32_t b_lane = (uint32_t)((r8 + ((grp >> 1) << 3) + wn * 64) * 80
                                       + (grp & 1) * 16);
    const int rbase = wm * 32 + (lane >> 2);

    // A-produce mapping: thread covers colgroup cg (8 cols) x rowgroup rg (16 rows)
    // NOTE: thread's 8 columns live entirely in chunk ca = cg>>2 (32 threads/chunk)
    const int cg = lane + (wid & 1) * 32;      // 0..63 -> cols cg*8..cg*8+7
    const int rg = wid >> 1;                   // 0..7  -> rows rg*16..rg*16+15
    const int ac0 = cg * 8;
    const int ca  = cg >> 2;                   // this thread's A chunk

    int s = 0;           // ring slot, continuous across tiles
    uint32_t ph = 0;     // ring phase
    int g = 0;           // global chunk counter

#pragma unroll 1
    for (int it = 0; it < nt; it++) {
        const int T   = bid + it * gx;
        const int bI  = T >> 6;
        const int mm0 = (T & 63) * TM;
        const uint32_t tpar = (uint32_t)(it & 1);

        mbar_wait(sbase + MBP_OFF, tpar);   // prologue params staged

        // ---- LN1 stats via closed form ----
        if (tid < TM) {
            const float p0 = pf[F_PTS + tid * 3 + 0];
            const float p1 = pf[F_PTS + tid * 3 + 1];
            const float p2 = pf[F_PTS + tid * 3 + 2];
            const float* L = pf + F_LC;
            const float sum = fmaf(p0, L[9], fmaf(p1, L[10], fmaf(p2, L[11], L[12])));
            float sq = L[13];
            sq = fmaf(p0 * p0, L[0], sq);
            sq = fmaf(2.f * p0 * p1, L[1], sq);
            sq = fmaf(2.f * p0 * p2, L[2], sq);
            sq = fmaf(p1 * p1, L[3], sq);
            sq = fmaf(2.f * p1 * p2, L[4], sq);
            sq = fmaf(p2 * p2, L[5], sq);
            sq = fmaf(2.f * p0, L[6], sq);
            sq = fmaf(2.f * p1, L[7], sq);
            sq = fmaf(2.f * p2, L[8], sq);
            const float mu = sum * (1.f / HH);
            pf[F_MU + tid] = mu;
            pf[F_RS + tid] = rsqrtf(sq * (1.f / HH) - mu * mu + EPSLN);
        }
        __syncthreads();

        // ---- produce A: 8 cols x 16 rows per thread; signal per-chunk readiness ----
        {
            float wA[8], wBv[8], wC[8], bC[8], gC[8], eC[8];
#pragma unroll
            for (int q = 0; q < 2; q++) {
                *(float4*)(wA  + q * 4) = *(const float4*)(pf + F_W1 + ac0 + q * 4);
                *(float4*)(wBv + q * 4) = *(const float4*)(pf + F_W1 + 512 + ac0 + q * 4);
                *(float4*)(wC  + q * 4) = *(const float4*)(pf + F_W1 + 1024 + ac0 + q * 4);
                *(float4*)(bC  + q * 4) = *(const float4*)(pf + F_B1 + ac0 + q * 4);
                *(float4*)(gC  + q * 4) = *(const float4*)(pf + F_G1 + ac0 + q * 4);
                *(float4*)(eC  + q * 4) = *(const float4*)(pf + F_BE1 + ac0 + q * 4);
            }
            uint32_t dst = sbase + A_OFF + (uint32_t)((rg * 16) * AROWB + ac0 * 2);
#pragma unroll 2
            for (int i = 0; i < 16; i++) {
                const int m = rg * 16 + i;
                const float p0 = pf[F_PTS + m * 3 + 0];
                const float p1 = pf[F_PTS + m * 3 + 1];
                const float p2 = pf[F_PTS + m * 3 + 2];
                const float rs = pf[F_RS + m];
                const float nms = -pf[F_MU + m] * rs;
                uint32_t u[4];
#pragma unroll
                for (int q = 0; q < 4; q++) {
                    const int j0 = q * 2, j1 = q * 2 + 1;
                    const float t0 = fmaf(p0, wA[j0], fmaf(p1, wBv[j0], fmaf(p2, wC[j0], bC[j0])));
                    const float t1 = fmaf(p0, wA[j1], fmaf(p1, wBv[j1], fmaf(p2, wC[j1], bC[j1])));
                    const float y0 = lrelu(fmaf(fmaf(t0, rs, nms), gC[j0], eC[j0]));
                    const float y1 = lrelu(fmaf(fmaf(t1, rs, nms), gC[j1], eC[j1]));
                    const __half2 h = __floats2half2_rn(y0, y1);
                    u[q] = *(const uint32_t*)&h;
                }
                asm volatile("st.shared.v4.b32 [%0], {%1,%2,%3,%4};"
                             :: "r"(dst), "r"(u[0]), "r"(u[1]), "r"(u[2]), "r"(u[3]));
                dst += AROWB;
            }
            mbar_arrive(sbase + MBA_OFF + 8u * ca);   // release: my chunk's cols done
        }
        // NO syncthreads: warps flow straight into mainloop, gated per chunk

        float acc[64];
#pragma unroll
        for (int i = 0; i < 64; i++) acc[i] = 0.f;

        // ---- mainloop: 16 chunks, gated by A-ready + B-full ----
#pragma unroll 1
        for (int c = 0; c < NCH; c++, g++) {
            mbar_wait(sbase + MBA_OFF + 8u * c, tpar);   // A chunk produced
            mbar_wait(sbase + MBF_OFF + 8u * s, ph);     // B chunk arrived

            const uint32_t abase = a_lane + (uint32_t)(c * 64);
            const uint32_t bbase = sbase + B0_OFF + (uint32_t)BCHUNK * s + b_lane;
#pragma unroll
            for (int ks = 0; ks < 2; ks++) {
                const uint32_t koff = (uint32_t)(ks * 32);
                uint32_t af[2][4], bf[4][4];
#pragma unroll
                for (int mt = 0; mt < 2; mt++)
                    ldsm4(af[mt], abase + (uint32_t)(mt * 16 * AROWB) + koff);
#pragma unroll
                for (int p = 0; p < 4; p++)
                    ldsm4(bf[p], bbase + (uint32_t)(p * 16 * 80) + koff);
#pragma unroll
                for (int mt = 0; mt < 2; mt++)
#pragma unroll
                    for (int p = 0; p < 4; p++) {
                        mma_f16(&acc[mt * 32 + (2 * p) * 4],     af[mt], bf[p][0], bf[p][1]);
                        mma_f16(&acc[mt * 32 + (2 * p + 1) * 4], af[mt], bf[p][2], bf[p][3]);
                    }
            }
            if (lane == 0) mbar_arrive(sbase + MBE_OFF + 8u * s);
            if (wid == (c & 15) && lane == 0 && g + NRING < totalChunks) {
                mbar_wait(sbase + MBE_OFF + 8u * s, ph);
                fill_B(g + NRING);
            }
            if (++s == NRING) { s = 0; ph ^= 1u; }
        }
        __syncthreads();

        mbar_wait(sbase + MBQ_OFF, tpar);   // epilogue params staged

        // ---- register epilogue ----
        {
            float sv[4] = {0.f, 0.f, 0.f, 0.f}, q[4] = {0.f, 0.f, 0.f, 0.f};
#pragma unroll
            for (int nt2 = 0; nt2 < 8; nt2++) {
                const int n = wn * 64 + nt2 * 8 + 2 * (lane & 3);
                const float2 bv = *(const float2*)(pf + F_B2 + n);
#pragma unroll
                for (int mt = 0; mt < 2; mt++) {
                    float* a4 = &acc[mt * 32 + nt2 * 4];
                    a4[0] += bv.x; a4[1] += bv.y; a4[2] += bv.x; a4[3] += bv.y;
                    const int j0 = mt * 2, j1 = mt * 2 + 1;
                    sv[j0] += a4[0] + a4[1];
                    q[j0] = fmaf(a4[0], a4[0], fmaf(a4[1], a4[1], q[j0]));
                    sv[j1] += a4[2] + a4[3];
                    q[j1] = fmaf(a4[2], a4[2], fmaf(a4[3], a4[3], q[j1]));
                }
            }
#pragma unroll
            for (int j = 0; j < 4; j++) {
                sv[j] += __shfl_xor_sync(0xffffffffu, sv[j], 1);
                sv[j] += __shfl_xor_sync(0xffffffffu, sv[j], 2);
                q[j] += __shfl_xor_sync(0xffffffffu, q[j], 1);
                q[j] += __shfl_xor_sync(0xffffffffu, q[j], 2);
            }
            if ((lane & 3) == 0) {
#pragma unroll
                for (int j = 0; j < 4; j++) {
                    const int r = rbase + 8 * j;
                    ep[E_S  + r * 4 + wn] = sv[j];
                    ep[E_S2 + r * 4 + wn] = q[j];
                }
            }
        }
        __syncthreads();

        {
            float mu[4], rs[4];
#pragma unroll
            for (int j = 0; j < 4; j++) {
                const int r = rbase + 8 * j;
                const float4 svv = *(const float4*)(ep + E_S  + r * 4);
                const float4 qv  = *(const float4*)(ep + E_S2 + r * 4);
                const float ss = (svv.x + svv.y) + (svv.z + svv.w);
                const float qq = (qv.x + qv.y) + (qv.z + qv.w);
                const float m_ = ss * (1.f / K2);
                mu[j] = m_;
                rs[j] = rsqrtf(qq * (1.f / K2) - m_ * m_ + EPSLN);
            }
            float o0[4] = {0,0,0,0}, o1[4] = {0,0,0,0}, o2[4] = {0,0,0,0};
#pragma unroll
            for (int nt2 = 0; nt2 < 8; nt2++) {
                const int n = wn * 64 + nt2 * 8 + 2 * (lane & 3);
                const float2 gv = *(const float2*)(pf + F_G2 + n);
                const float2 ev = *(const float2*)(pf + F_BE2 + n);
                const float w3a0 = pf[F_W3 + n * 3 + 0];
                const float w3a1 = pf[F_W3 + n * 3 + 1];
                const float w3a2 = pf[F_W3 + n * 3 + 2];
                const float w3b0 = pf[F_W3 + n * 3 + 3];
                const float w3b1 = pf[F_W3 + n * 3 + 4];
                const float w3b2 = pf[F_W3 + n * 3 + 5];
#pragma unroll
                for (int mt = 0; mt < 2; mt++) {
                    const float* a4 = &acc[mt * 32 + nt2 * 4];
#pragma unroll
                    for (int hh2 = 0; hh2 < 2; hh2++) {
                        const int j = mt * 2 + hh2;
                        const float ya = lrelu(fmaf((a4[hh2 * 2 + 0] - mu[j]) * rs[j], gv.x, ev.x));
                        const float yb = lrelu(fmaf((a4[hh2 * 2 + 1] - mu[j]) * rs[j], gv.y, ev.y));
                        o0[j] = fmaf(ya, w3a0, fmaf(yb, w3b0, o0[j]));
                        o1[j] = fmaf(ya, w3a1, fmaf(yb, w3b1, o1[j]));
                        o2[j] = fmaf(ya, w3a2, fmaf(yb, w3b2, o2[j]));
                    }
                }
            }
#pragma unroll
            for (int j = 0; j < 4; j++) {
                o0[j] += __shfl_xor_sync(0xffffffffu, o0[j], 1);
                o0[j] += __shfl_xor_sync(0xffffffffu, o0[j], 2);
                o1[j] += __shfl_xor_sync(0xffffffffu, o1[j], 1);
                o1[j] += __shfl_xor_sync(0xffffffffu, o1[j], 2);
                o2[j] += __shfl_xor_sync(0xffffffffu, o2[j], 1);
                o2[j] += __shfl_xor_sync(0xffffffffu, o2[j], 2);
            }
            if ((lane & 3) == 0) {
#pragma unroll
                for (int j = 0; j < 4; j++) {
                    const int r = rbase + 8 * j;
                    ep[E_O + r * 12 + wn * 3 + 0] = o0[j];
                    ep[E_O + r * 12 + wn * 3 + 1] = o1[j];
                    ep[E_O + r * 12 + wn * 3 + 2] = o2[j];
                }
            }
        }
        __syncthreads();   // last pf(epi) read done; all producers past A writes

        if (tid == 0 && it + 1 < nt) {   // prefetch next tile's params (region now dead)
            issue_pro(T + gx);
            issue_epi(T + gx);
        }

        if (tid < TM) {
            const int r = tid;
            const int cc = __ldg(cat + bI);
            float v0 = __ldg(b3 + cc * 3 + 0);
            float v1 = __ldg(b3 + cc * 3 + 1);
            float v2 = __ldg(b3 + cc * 3 + 2);
#pragma unroll
            for (int w = 0; w < 4; w++) {
                v0 += ep[E_O + r * 12 + w * 3 + 0];
                v1 += ep[E_O + r * 12 + w * 3 + 1];
                v2 += ep[E_O + r * 12 + w * 3 + 2];
            }
            float* op = out + (size_t)(bI * NN + mm0 + r) * 3;
            op[0] = v0; op[1] = v1; op[2] = v2;
        }
        __syncthreads();   // ep stable until next tile's epilogue
    }
}

extern "C" void kernel_launch(void* const* d_in, const int* in_sizes, int n_in,
                              void* d_out, int out_size)
{
    const float* points = (const float*)d_in[0];
    const int*   cat    = (const int*)  d_in[1];
    const float* W1     = (const float*)d_in[2];
    const float* b1     = (const float*)d_in[3];
    const float* g1     = (const float*)d_in[4];
    const float* be1    = (const float*)d_in[5];
    const float* W2     = (const float*)d_in[6];
    const float* b2     = (const float*)d_in[7];
    const float* g2     = (const float*)d_in[8];
    const float* be2    = (const float*)d_in[9];
    const float* W3     = (const float*)d_in[10];
    const float* b3     = (const float*)d_in[11];
    float* out = (float*)d_out;

    cudaFuncSetAttribute(shape_prior_mma,
                         cudaFuncAttributeMaxDynamicSharedMemorySize, SMEM_TOTAL);

    pack_w2<<<dim3(HH / 32, K2 / 32, NE), dim3(32, 8)>>>(W2);
    pack_ln1<<<NE, 512>>>(W1, b1);
    shape_prior_mma<<<GRIDX, THREADS, SMEM_TOTAL>>>(
        points, cat, W1, b1, g1, be1, b2, g2, be2, W3, b3, out);
}

// round 17
// speedup vs baseline: 1.0341x; 1.0341x over previous
#include <cuda_runtime.h>
#include <cuda_fp16.h>
#include <cstdint>

#define BB      32
#define NN      8192
#define HH      512
#define K2      256
#define TM      128
#define THREADS 512
#define NWARP   16
#define EPSLN   1e-5f
#define SLOPE   0.2f
#define KC      32
#define NCH     (HH / KC)       // 16 k-chunks per tile
#define NRING   3
#define NE      10
#define NTILES  ((NN / TM) * BB)   // 2048
#define GRIDX   148

// B row: 32 fp16 (64 B) + 16 B pad = 80 B (40 halves) -- conflict-free for ldsm
#define BROWH   40
#define BCHUNK  (K2 * 80)               // 20480 B per chunk

// A tile in smem: 128 rows x (512 fp16 = 1024 B + 16 pad) = 1040 B stride
#define AROWB   1040
#define A_SIZE  (TM * AROWB)            // 133120 B

__device__ __half g_W2C[(size_t)NE * NCH * K2 * BROWH];
__device__ float g_LN1[NE * 16];

// ---------------- smem layout (bytes) ----------------
#define A_OFF  0u
#define B0_OFF 133120u                  // 3 x 20480 -> ends 194560
#define EP_OFF 194560u                  // epilogue partials: 2560 floats = 10240 B
#define P_OFF  204800u
#define F_W1    0             // [3][512]
#define F_B1    1536
#define F_G1    2048
#define F_BE1   2560
#define F_B2    3072
#define F_G2    3328
#define F_BE2   3584
#define F_W3    3840          // [256][3]
#define F_PTS   4612          // [128][3]
#define F_MU    4996
#define F_RS    5124
#define F_LC    5252          // 16 LN1 constants
#define F_END   5268
#define MBF_OFF (P_OFF + F_END * 4)    // 3 x full
#define MBE_OFF (MBF_OFF + 24)         // 3 x empty
#define MBP_OFF (MBE_OFF + 24)         // prologue-params staging
#define MBQ_OFF (MBP_OFF + 8)          // epilogue-params staging
#define SMEM_TOTAL (MBQ_OFF + 8)       // 225936 B
#define PRO_BYTES (6144 + 2048 * 3 + 1536 + 64)   // 13888
#define EPI_BYTES (1024 * 3 + 3072)               // 6144
// epilogue partials (float idx rel. to EP_OFF)
#define E_S     0      // [128][4]
#define E_S2    512    // [128][4]
#define E_O     1024   // [128][4][3]

__device__ __forceinline__ uint32_t smem_u32(const void* p) {
    uint32_t a;
    asm("{ .reg .u64 t; cvta.to.shared.u64 t, %1; cvt.u32.u64 %0, t; }" : "=r"(a) : "l"(p));
    return a;
}
__device__ __forceinline__ float warp_sum(float v) {
#pragma unroll
    for (int o = 16; o; o >>= 1) v += __shfl_xor_sync(0xffffffffu, v, o);
    return v;
}
__device__ __forceinline__ void ldsm4(uint32_t* r, uint32_t addr) {
    asm volatile("ldmatrix.sync.aligned.m8n8.x4.shared.b16 {%0,%1,%2,%3}, [%4];"
                 : "=r"(r[0]), "=r"(r[1]), "=r"(r[2]), "=r"(r[3]) : "r"(addr));
}
__device__ __forceinline__ void mma_f16(float* c, const uint32_t* a, uint32_t b0, uint32_t b1) {
    asm volatile("mma.sync.aligned.m16n8k16.row.col.f32.f16.f16.f32 "
                 "{%0,%1,%2,%3}, {%4,%5,%6,%7}, {%8,%9}, {%0,%1,%2,%3};"
                 : "+f"(c[0]), "+f"(c[1]), "+f"(c[2]), "+f"(c[3])
                 : "r"(a[0]), "r"(a[1]), "r"(a[2]), "r"(a[3]), "r"(b0), "r"(b1));
}
__device__ __forceinline__ void mbar_wait(uint32_t addr, uint32_t parity) {
    asm volatile(
        "{\n\t.reg .pred P;\n\t"
        "WL_%=:\n\t"
        "mbarrier.try_wait.parity.acquire.cta.shared::cta.b64 P, [%0], %1, 0x989680;\n\t"
        "@P bra.uni WD_%=;\n\t"
        "bra.uni WL_%=;\n\t"
        "WD_%=:\n\t}"
        :: "r"(addr), "r"(parity) : "memory");
}
__device__ __forceinline__ void bulk_in(uint32_t dst, const void* src, uint32_t bytes,
                                        uint32_t mbar) {
    asm volatile(
        "cp.async.bulk.shared::cluster.global.mbarrier::complete_tx::bytes "
        "[%0], [%1], %2, [%3];"
        :: "r"(dst), "l"(src), "r"(bytes), "r"(mbar) : "memory");
}
__device__ __forceinline__ void expect_tx(uint32_t mbar, uint32_t bytes) {
    asm volatile("mbarrier.arrive.expect_tx.shared.b64 _, [%0], %1;"
                 :: "r"(mbar), "r"(bytes) : "memory");
}
__device__ __forceinline__ void mbar_arrive(uint32_t mbar) {
    asm volatile("mbarrier.arrive.shared.b64 _, [%0];" :: "r"(mbar) : "memory");
}
__device__ __forceinline__ float lrelu(float y) { return fmaxf(y, SLOPE * y); }

// ------------- fused pack: W2 transpose/fp16 chunk image + LN1 constants -------
// grid (17, 8, 10), block (32, 8):
//   blockIdx.x < 16            -> W2 pack tile (kb = x*32, nb = y*32, expert z)
//   blockIdx.x == 16 && y == 0 -> LN1 closed-form constants for expert z
__global__ void pack_all(const float* __restrict__ W2,
                         const float* __restrict__ W1, const float* __restrict__ b1) {
    __shared__ float t[32][33];
    const int e  = blockIdx.z;
    const int tx = threadIdx.x, ty = threadIdx.y;
    const int tid = ty * 32 + tx;

    if (blockIdx.x < 16) {
        const int kb = blockIdx.x * 32, nb = blockIdx.y * 32;
        const float* src = W2 + e * HH * K2;
#pragma unroll
        for (int r = 0; r < 32; r += 8)
            t[ty + r][tx] = src[(kb + ty + r) * K2 + nb + tx];
        __syncthreads();
        const int ch = kb >> 5;
        __half* dst = g_W2C + ((size_t)(e * NCH + ch) * K2) * BROWH;
#pragma unroll
        for (int r = 0; r < 32; r += 8)
            dst[(size_t)(nb + ty + r) * BROWH + tx] = __float2half_rn(t[tx][ty + r]);
        return;
    }
    if (blockIdx.y != 0) return;

    // LN1 constants for expert e (256 threads, 2 elements each)
    float* red = &t[0][0];   // reuse shared: [8][14]
    const float* w = W1 + e * 3 * HH;
    float vals[14];
#pragma unroll
    for (int i = 0; i < 14; i++) vals[i] = 0.f;
#pragma unroll
    for (int h = 0; h < 2; h++) {
        const int k = tid + h * 256;
        const float w0 = w[k], w1 = w[HH + k], w2 = w[2 * HH + k];
        const float bb = b1[e * HH + k];
        vals[0] += w0 * w0;  vals[1] += w0 * w1;  vals[2] += w0 * w2;
        vals[3] += w1 * w1;  vals[4] += w1 * w2;  vals[5] += w2 * w2;
        vals[6] += w0 * bb;  vals[7] += w1 * bb;  vals[8] += w2 * bb;
        vals[9] += w0;       vals[10] += w1;      vals[11] += w2;
        vals[12] += bb;      vals[13] += bb * bb;
    }
#pragma unroll
    for (int i = 0; i < 14; i++) vals[i] = warp_sum(vals[i]);
    const int wq = tid >> 5, lane = tid & 31;
    if (lane == 0)
#pragma unroll
        for (int i = 0; i < 14; i++) red[wq * 14 + i] = vals[i];
    __syncthreads();
    if (tid < 14) {
        float s = 0.f;
#pragma unroll
        for (int j = 0; j < 8; j++) s += red[j * 14 + tid];
        g_LN1[e * 16 + tid] = s;
    }
    if (tid >= 14 && tid < 16) g_LN1[e * 16 + tid] = 0.f;
}

extern __shared__ char smem_raw[];

__global__ __launch_bounds__(THREADS, 1)
void shape_prior_mma(const float* __restrict__ points, const int* __restrict__ cat,
                     const float* __restrict__ W1, const float* __restrict__ b1,
                     const float* __restrict__ g1, const float* __restrict__ be1,
                     const float* __restrict__ b2, const float* __restrict__ g2,
                     const float* __restrict__ be2,
                     const float* __restrict__ W3, const float* __restrict__ b3,
                     float* __restrict__ out)
{
    float* pf = (float*)(smem_raw + P_OFF);
    float* ep = (float*)(smem_raw + EP_OFF);
    const int tid  = threadIdx.x;
    const int wid  = tid >> 5;
    const int lane = tid & 31;
    const int bid  = blockIdx.x;
    const int gx   = gridDim.x;
    const uint32_t sbase = smem_u32(smem_raw);
    const uint32_t pbase = sbase + P_OFF;

    const int nt = (NTILES - bid + gx - 1) / gx;
    if (nt <= 0) return;
    const int totalChunks = nt * NCH;

    if (tid == 0) {
#pragma unroll
        for (int j = 0; j < NRING; j++) {
            asm volatile("mbarrier.init.shared.b64 [%0], 1;"
                         :: "r"(sbase + MBF_OFF + 8u * j) : "memory");
            asm volatile("mbarrier.init.shared.b64 [%0], %1;"
                         :: "r"(sbase + MBE_OFF + 8u * j), "r"(NWARP) : "memory");
        }
        asm volatile("mbarrier.init.shared.b64 [%0], 1;"
                     :: "r"(sbase + MBP_OFF) : "memory");
        asm volatile("mbarrier.init.shared.b64 [%0], 1;"
                     :: "r"(sbase + MBQ_OFF) : "memory");
    }
    __syncthreads();

    auto issue_pro = [&](int T) {
        const int bI = T >> 6, mm0 = (T & 63) * TM;
        const int cc = __ldg(cat + bI);
        const uint32_t mb = sbase + MBP_OFF;
        expect_tx(mb, PRO_BYTES);
        bulk_in(pbase + F_W1  * 4, W1  + (size_t)cc * 3 * HH, 6144, mb);
        bulk_in(pbase + F_B1  * 4, b1  + (size_t)cc * HH,     2048, mb);
        bulk_in(pbase + F_G1  * 4, g1  + (size_t)cc * HH,     2048, mb);
        bulk_in(pbase + F_BE1 * 4, be1 + (size_t)cc * HH,     2048, mb);
        bulk_in(pbase + F_PTS * 4, points + (size_t)(bI * NN + mm0) * 3, 1536, mb);
        bulk_in(pbase + F_LC  * 4, g_LN1 + cc * 16, 64, mb);
    };
    auto issue_epi = [&](int T) {
        const int cc = __ldg(cat + (T >> 6));
        const uint32_t mb = sbase + MBQ_OFF;
        expect_tx(mb, EPI_BYTES);
        bulk_in(pbase + F_B2  * 4, b2  + (size_t)cc * K2,     1024, mb);
        bulk_in(pbase + F_G2  * 4, g2  + (size_t)cc * K2,     1024, mb);
        bulk_in(pbase + F_BE2 * 4, be2 + (size_t)cc * K2,     1024, mb);
        bulk_in(pbase + F_W3  * 4, W3  + (size_t)cc * K2 * 3, 3072, mb);
    };
    auto fill_B = [&](int g) {   // global chunk index
        const int T  = bid + (g >> 4) * gx;
        const int cc = __ldg(cat + (T >> 6));
        const int sl = g % NRING;
        const uint32_t mb = sbase + MBF_OFF + 8u * sl;
        expect_tx(mb, BCHUNK);
        bulk_in(sbase + B0_OFF + (uint32_t)BCHUNK * sl,
                g_W2C + ((size_t)(cc * NCH + (g & 15)) * K2) * BROWH, BCHUNK, mb);
    };

    if (tid == 0) {
        issue_pro(bid);
        issue_epi(bid);
#pragma unroll
        for (int j = 0; j < NRING; j++)
            if (j < totalChunks) fill_B(j);
    }

    // warp tile 32x64: wm = wid>>2 (rows wm*32..), wn = wid&3 (cols wn*64..)
    const int wm = wid >> 2, wn = wid & 3;
    const int grp = lane >> 3, r8 = lane & 7;
    const uint32_t a_lane = sbase + A_OFF
                          + (uint32_t)((r8 + ((grp & 1) << 3) + wm * 32) * AROWB
                                       + (grp >> 1) * 16);
    const uint32_t b_lane = (uint32_t)((r8 + ((grp >> 1) << 3) + wn * 64) * 80
                                       + (grp & 1) * 16);
    const int rbase = wm * 32 + (lane >> 2);

    // A-produce mapping: thread covers colgroup cg (8 cols) x rowgroup rg (16 rows)
    const int cg = lane + (wid & 1) * 32;      // 0..63 -> cols cg*8..cg*8+7
    const int rg = wid >> 1;                   // 0..7  -> rows rg*16..rg*16+15
    const int ac0 = cg * 8;

    int s = 0;           // ring slot, continuous across tiles
    uint32_t ph = 0;     // ring phase
    int g = 0;           // global chunk counter

#pragma unroll 1
    for (int it = 0; it < nt; it++) {
        const int T   = bid + it * gx;
        const int bI  = T >> 6;
        const int mm0 = (T & 63) * TM;
        const uint32_t tpar = (uint32_t)(it & 1);

        mbar_wait(sbase + MBP_OFF, tpar);   // prologue params staged

        // ---- LN1 stats via closed form ----
        if (tid < TM) {
            const float p0 = pf[F_PTS + tid * 3 + 0];
            const float p1 = pf[F_PTS + tid * 3 + 1];
            const float p2 = pf[F_PTS + tid * 3 + 2];
            const float* L = pf + F_LC;
            const float sum = fmaf(p0, L[9], fmaf(p1, L[10], fmaf(p2, L[11], L[12])));
            float sq = L[13];
            sq = fmaf(p0 * p0, L[0], sq);
            sq = fmaf(2.f * p0 * p1, L[1], sq);
            sq = fmaf(2.f * p0 * p2, L[2], sq);
            sq = fmaf(p1 * p1, L[3], sq);
            sq = fmaf(2.f * p1 * p2, L[4], sq);
            sq = fmaf(p2 * p2, L[5], sq);
            sq = fmaf(2.f * p0, L[6], sq);
            sq = fmaf(2.f * p1, L[7], sq);
            sq = fmaf(2.f * p2, L[8], sq);
            const float mu = sum * (1.f / HH);
            pf[F_MU + tid] = mu;
            pf[F_RS + tid] = rsqrtf(sq * (1.f / HH) - mu * mu + EPSLN);
        }
        __syncthreads();

        // ---- produce ENTIRE A tile: 8 cols x 16 rows per thread ----
        {
            float wA[8], wBv[8], wC[8], bC[8], gC[8], eC[8];
#pragma unroll
            for (int q = 0; q < 2; q++) {
                *(float4*)(wA  + q * 4) = *(const float4*)(pf + F_W1 + ac0 + q * 4);
                *(float4*)(wBv + q * 4) = *(const float4*)(pf + F_W1 + 512 + ac0 + q * 4);
                *(float4*)(wC  + q * 4) = *(const float4*)(pf + F_W1 + 1024 + ac0 + q * 4);
                *(float4*)(bC  + q * 4) = *(const float4*)(pf + F_B1 + ac0 + q * 4);
                *(float4*)(gC  + q * 4) = *(const float4*)(pf + F_G1 + ac0 + q * 4);
                *(float4*)(eC  + q * 4) = *(const float4*)(pf + F_BE1 + ac0 + q * 4);
            }
            uint32_t dst = sbase + A_OFF + (uint32_t)((rg * 16) * AROWB + ac0 * 2);
#pragma unroll 2
            for (int i = 0; i < 16; i++) {
                const int m = rg * 16 + i;
                const float p0 = pf[F_PTS + m * 3 + 0];   // broadcast (warp-uniform)
                const float p1 = pf[F_PTS + m * 3 + 1];
                const float p2 = pf[F_PTS + m * 3 + 2];
                const float rs = pf[F_RS + m];
                const float nms = -pf[F_MU + m] * rs;     // y = t*rs + nms
                uint32_t u[4];
#pragma unroll
                for (int q = 0; q < 4; q++) {
                    const int j0 = q * 2, j1 = q * 2 + 1;
                    const float t0 = fmaf(p0, wA[j0], fmaf(p1, wBv[j0], fmaf(p2, wC[j0], bC[j0])));
                    const float t1 = fmaf(p0, wA[j1], fmaf(p1, wBv[j1], fmaf(p2, wC[j1], bC[j1])));
                    const float y0 = lrelu(fmaf(fmaf(t0, rs, nms), gC[j0], eC[j0]));
                    const float y1 = lrelu(fmaf(fmaf(t1, rs, nms), gC[j1], eC[j1]));
                    const __half2 h = __floats2half2_rn(y0, y1);
                    u[q] = *(const uint32_t*)&h;
                }
                asm volatile("st.shared.v4.b32 [%0], {%1,%2,%3,%4};"
                             :: "r"(dst), "r"(u[0]), "r"(u[1]), "r"(u[2]), "r"(u[3]));
                dst += AROWB;
            }
        }
        __syncthreads();   // A visible; prologue-params region now dead

        if (tid == 0 && it + 1 < nt) issue_pro(T + gx);   // prefetch next prologue

        float acc[64];
#pragma unroll
        for (int i = 0; i < 64; i++) acc[i] = 0.f;

        // ---- mainloop: 16 chunks, no CTA barriers ----
#pragma unroll 1
        for (int c = 0; c < NCH; c++, g++) {
            mbar_wait(sbase + MBF_OFF + 8u * s, ph);

            const uint32_t abase = a_lane + (uint32_t)(c * 64);
            const uint32_t bbase = sbase + B0_OFF + (uint32_t)BCHUNK * s + b_lane;
#pragma unroll
            for (int ks = 0; ks < 2; ks++) {
                const uint32_t koff = (uint32_t)(ks * 32);
                uint32_t af[2][4], bf[4][4];
#pragma unroll
                for (int mt = 0; mt < 2; mt++)
                    ldsm4(af[mt], abase + (uint32_t)(mt * 16 * AROWB) + koff);
#pragma unroll
                for (int p = 0; p < 4; p++)
                    ldsm4(bf[p], bbase + (uint32_t)(p * 16 * 80) + koff);
#pragma unroll
                for (int mt = 0; mt < 2; mt++)
#pragma unroll
                    for (int p = 0; p < 4; p++) {
                        mma_f16(&acc[mt * 32 + (2 * p) * 4],     af[mt], bf[p][0], bf[p][1]);
                        mma_f16(&acc[mt * 32 + (2 * p + 1) * 4], af[mt], bf[p][2], bf[p][3]);
                    }
            }
            if (lane == 0) mbar_arrive(sbase + MBE_OFF + 8u * s);
            // rotated producer: warp (c & 15) lane 0 refills this slot for chunk g+NRING
            if (wid == (c & 15) && lane == 0 && g + NRING < totalChunks) {
                mbar_wait(sbase + MBE_OFF + 8u * s, ph);
                fill_B(g + NRING);
            }
            if (++s == NRING) { s = 0; ph ^= 1u; }
        }
        __syncthreads();

        mbar_wait(sbase + MBQ_OFF, tpar);   // epilogue params staged

        // ---- register epilogue ----
        {
            float sv[4] = {0.f, 0.f, 0.f, 0.f}, q[4] = {0.f, 0.f, 0.f, 0.f};
#pragma unroll
            for (int nt2 = 0; nt2 < 8; nt2++) {
                const int n = wn * 64 + nt2 * 8 + 2 * (lane & 3);
                const float2 bv = *(const float2*)(pf + F_B2 + n);
#pragma unroll
                for (int mt = 0; mt < 2; mt++) {
                    float* a4 = &acc[mt * 32 + nt2 * 4];
                    a4[0] += bv.x; a4[1] += bv.y; a4[2] += bv.x; a4[3] += bv.y;
                    const int j0 = mt * 2, j1 = mt * 2 + 1;
                    sv[j0] += a4[0] + a4[1];
                    q[j0] = fmaf(a4[0], a4[0], fmaf(a4[1], a4[1], q[j0]));
                    sv[j1] += a4[2] + a4[3];
                    q[j1] = fmaf(a4[2], a4[2], fmaf(a4[3], a4[3], q[j1]));
                }
            }
#pragma unroll
            for (int j = 0; j < 4; j++) {
                sv[j] += __shfl_xor_sync(0xffffffffu, sv[j], 1);
                sv[j] += __shfl_xor_sync(0xffffffffu, sv[j], 2);
                q[j] += __shfl_xor_sync(0xffffffffu, q[j], 1);
                q[j] += __shfl_xor_sync(0xffffffffu, q[j], 2);
            }
            if ((lane & 3) == 0) {
#pragma unroll
                for (int j = 0; j < 4; j++) {
                    const int r = rbase + 8 * j;
                    ep[E_S  + r * 4 + wn] = sv[j];
                    ep[E_S2 + r * 4 + wn] = q[j];
                }
            }
        }
        __syncthreads();

        {
            float mu[4], rs[4];
#pragma unroll
            for (int j = 0; j < 4; j++) {
                const int r = rbase + 8 * j;
                const float4 svv = *(const float4*)(ep + E_S  + r * 4);
                const float4 qv  = *(const float4*)(ep + E_S2 + r * 4);
                const float ss = (svv.x + svv.y) + (svv.z + svv.w);
                const float qq = (qv.x + qv.y) + (qv.z + qv.w);
                const float m_ = ss * (1.f / K2);
                mu[j] = m_;
                rs[j] = rsqrtf(qq * (1.f / K2) - m_ * m_ + EPSLN);
            }
            float o0[4] = {0,0,0,0}, o1[4] = {0,0,0,0}, o2[4] = {0,0,0,0};
#pragma unroll
            for (int nt2 = 0; nt2 < 8; nt2++) {
                const int n = wn * 64 + nt2 * 8 + 2 * (lane & 3);
                const float2 gv = *(const float2*)(pf + F_G2 + n);
                const float2 ev = *(const float2*)(pf + F_BE2 + n);
                const float w3a0 = pf[F_W3 + n * 3 + 0];
                const float w3a1 = pf[F_W3 + n * 3 + 1];
                const float w3a2 = pf[F_W3 + n * 3 + 2];
                const float w3b0 = pf[F_W3 + n * 3 + 3];
                const float w3b1 = pf[F_W3 + n * 3 + 4];
                const float w3b2 = pf[F_W3 + n * 3 + 5];
#pragma unroll
                for (int mt = 0; mt < 2; mt++) {
                    const float* a4 = &acc[mt * 32 + nt2 * 4];
#pragma unroll
                    for (int hh2 = 0; hh2 < 2; hh2++) {
                        const int j = mt * 2 + hh2;
                        const float ya = lrelu(fmaf((a4[hh2 * 2 + 0] - mu[j]) * rs[j], gv.x, ev.x));
                        const float yb = lrelu(fmaf((a4[hh2 * 2 + 1] - mu[j]) * rs[j], gv.y, ev.y));
                        o0[j] = fmaf(ya, w3a0, fmaf(yb, w3b0, o0[j]));
                        o1[j] = fmaf(ya, w3a1, fmaf(yb, w3b1, o1[j]));
                        o2[j] = fmaf(ya, w3a2, fmaf(yb, w3b2, o2[j]));
                    }
                }
            }
#pragma unroll
            for (int j = 0; j < 4; j++) {
                o0[j] += __shfl_xor_sync(0xffffffffu, o0[j], 1);
                o0[j] += __shfl_xor_sync(0xffffffffu, o0[j], 2);
                o1[j] += __shfl_xor_sync(0xffffffffu, o1[j], 1);
                o1[j] += __shfl_xor_sync(0xffffffffu, o1[j], 2);
                o2[j] += __shfl_xor_sync(0xffffffffu, o2[j], 1);
                o2[j] += __shfl_xor_sync(0xffffffffu, o2[j], 2);
            }
            if ((lane & 3) == 0) {
#pragma unroll
                for (int j = 0; j < 4; j++) {
                    const int r = rbase + 8 * j;
                    ep[E_O + r * 12 + wn * 3 + 0] = o0[j];
                    ep[E_O + r * 12 + wn * 3 + 1] = o1[j];
                    ep[E_O + r * 12 + wn * 3 + 2] = o2[j];
                }
            }
        }
        __syncthreads();   // last pf(epi) read done

        if (tid == 0 && it + 1 < nt) issue_epi(T + gx);   // prefetch next epilogue params

        if (tid < TM) {
            const int r = tid;
            const int cc = __ldg(cat + bI);
            float v0 = __ldg(b3 + cc * 3 + 0);
            float v1 = __ldg(b3 + cc * 3 + 1);
            float v2 = __ldg(b3 + cc * 3 + 2);
#pragma unroll
            for (int w = 0; w < 4; w++) {
                v0 += ep[E_O + r * 12 + w * 3 + 0];
                v1 += ep[E_O + r * 12 + w * 3 + 1];
                v2 += ep[E_O + r * 12 + w * 3 + 2];
            }
            float* op = out + (size_t)(bI * NN + mm0 + r) * 3;
            op[0] = v0; op[1] = v1; op[2] = v2;
        }
        __syncthreads();   // ep stable until next tile's epilogue
    }
}

extern "C" void kernel_launch(void* const* d_in, const int* in_sizes, int n_in,
                              void* d_out, int out_size)
{
    const float* points = (const float*)d_in[0];
    const int*   cat    = (const int*)  d_in[1];
    const float* W1     = (const float*)d_in[2];
    const float* b1     = (const float*)d_in[3];
    const float* g1     = (const float*)d_in[4];
    const float* be1    = (const float*)d_in[5];
    const float* W2     = (const float*)d_in[6];
    const float* b2     = (const float*)d_in[7];
    const float* g2     = (const float*)d_in[8];
    const float* be2    = (const float*)d_in[9];
    const float* W3     = (const float*)d_in[10];
    const float* b3     = (const float*)d_in[11];
    float* out = (float*)d_out;

    cudaFuncSetAttribute(shape_prior_mma,
                         cudaFuncAttributeMaxDynamicSharedMemorySize, SMEM_TOTAL);

    pack_all<<<dim3(17, 8, NE), dim3(32, 8)>>>(W2, W1, b1);
    shape_prior_mma<<<GRIDX, THREADS, SMEM_TOTAL>>>(
        points, cat, W1, b1, g1, be1, b2, g2, be2, W3, b3, out);
}